// round 2
// baseline (speedup 1.0000x reference)
#include <cuda_runtime.h>

#define NB 8
#define LC 2048
#define LQ 512
#define DD 768

// Scratch: tempT[b][c][q] (then alpha in-place). 33.5 MB static device array.
__device__ float g_tmp[NB * LC * LQ];

// ---------------------------------------------------------------------------
// GEMM1 (NT): tempT[b][c][q] = sum_d ctx[b][c][d] * qry[b][q][d]
// A = ctx[b] [LC][DD] (K-major), B = qry[b] [LQ][DD] (K-major)
// Tile: BM=128 (c), BN=128 (q), BK=16, 256 threads, 8x8 micro-tile.
// ---------------------------------------------------------------------------
__global__ __launch_bounds__(256) void k_gemm1(const float* __restrict__ ctx,
                                               const float* __restrict__ qry) {
    __shared__ float As[16][128];  // [k][m]
    __shared__ float Bs[16][128];  // [k][n]

    const int b  = blockIdx.z;
    const int m0 = blockIdx.y * 128;  // c offset
    const int n0 = blockIdx.x * 128;  // q offset
    const float* Ab = ctx + ((size_t)b * LC + m0) * DD;
    const float* Bb = qry + ((size_t)b * LQ + n0) * DD;

    const int tid = threadIdx.x;
    const int tx = tid & 15;
    const int ty = tid >> 4;

    float acc[8][8];
#pragma unroll
    for (int i = 0; i < 8; ++i)
#pragma unroll
        for (int j = 0; j < 8; ++j) acc[i][j] = 0.0f;

    for (int k0 = 0; k0 < DD; k0 += 16) {
#pragma unroll
        for (int i = 0; i < 2; ++i) {
            int f   = tid + i * 256;      // float4 id, 0..511
            int row = f >> 2;             // 0..127
            int kc  = (f & 3) * 4;        // 0,4,8,12
            float4 av = *(const float4*)(Ab + (size_t)row * DD + k0 + kc);
            float4 bv = *(const float4*)(Bb + (size_t)row * DD + k0 + kc);
            As[kc + 0][row] = av.x; As[kc + 1][row] = av.y;
            As[kc + 2][row] = av.z; As[kc + 3][row] = av.w;
            Bs[kc + 0][row] = bv.x; Bs[kc + 1][row] = bv.y;
            Bs[kc + 2][row] = bv.z; Bs[kc + 3][row] = bv.w;
        }
        __syncthreads();

#pragma unroll
        for (int k = 0; k < 16; ++k) {
            float ar[8], br[8];
            *(float4*)&ar[0] = *(const float4*)&As[k][ty * 8];
            *(float4*)&ar[4] = *(const float4*)&As[k][ty * 8 + 4];
            *(float4*)&br[0] = *(const float4*)&Bs[k][tx * 8];
            *(float4*)&br[4] = *(const float4*)&Bs[k][tx * 8 + 4];
#pragma unroll
            for (int i = 0; i < 8; ++i)
#pragma unroll
                for (int j = 0; j < 8; ++j)
                    acc[i][j] = fmaf(ar[i], br[j], acc[i][j]);
        }
        __syncthreads();
    }

#pragma unroll
    for (int i = 0; i < 8; ++i) {
        int c = m0 + ty * 8 + i;
        float* op = g_tmp + ((size_t)(b * LC + c)) * LQ + n0 + tx * 8;
        float4 v0 = make_float4(acc[i][0], acc[i][1], acc[i][2], acc[i][3]);
        float4 v1 = make_float4(acc[i][4], acc[i][5], acc[i][6], acc[i][7]);
        *(float4*)(op)     = v0;
        *(float4*)(op + 4) = v1;
    }
}

// ---------------------------------------------------------------------------
// Softmax over contiguous rows of length LQ=512 (this is the q axis).
// One block (256 threads) per row; 2 elements/thread.
// ---------------------------------------------------------------------------
__global__ __launch_bounds__(256) void k_softmax() {
    const int row = blockIdx.x;  // b*LC + c
    float2* p = (float2*)(g_tmp + (size_t)row * LQ);
    const int tid = threadIdx.x;

    float2 v = p[tid];
    float m = fmaxf(v.x, v.y);
#pragma unroll
    for (int o = 16; o > 0; o >>= 1)
        m = fmaxf(m, __shfl_xor_sync(0xffffffffu, m, o));

    __shared__ float smax[8];
    __shared__ float ssum[8];
    if ((tid & 31) == 0) smax[tid >> 5] = m;
    __syncthreads();
    float bm = smax[0];
#pragma unroll
    for (int i = 1; i < 8; ++i) bm = fmaxf(bm, smax[i]);

    float e0 = __expf(v.x - bm);
    float e1 = __expf(v.y - bm);
    float s = e0 + e1;
#pragma unroll
    for (int o = 16; o > 0; o >>= 1)
        s += __shfl_xor_sync(0xffffffffu, s, o);
    if ((tid & 31) == 0) ssum[tid >> 5] = s;
    __syncthreads();
    float bs = 0.0f;
#pragma unroll
    for (int i = 0; i < 8; ++i) bs += ssum[i];

    float inv = 1.0f / bs;
    p[tid] = make_float2(e0 * inv, e1 * inv);
}

// ---------------------------------------------------------------------------
// GEMM2 (NN) + gate: out[b][c][d] = ctx[b][c][d] * sum_q alpha[b][c][q]*qry[b][q][d]
// A = alphaT[b] [LC][LQ] (K-major), B = qry[b] [LQ][DD] (N-major)
// Tile: BM=128 (c), BN=128 (d), BK=16, 256 threads, 8x8 micro-tile.
// ---------------------------------------------------------------------------
__global__ __launch_bounds__(256) void k_gemm2(const float* __restrict__ ctx,
                                               const float* __restrict__ qry,
                                               float* __restrict__ out) {
    __shared__ float As[16][128];  // [k][m]
    __shared__ float Bs[16][128];  // [k][n]

    const int b  = blockIdx.z;
    const int m0 = blockIdx.y * 128;  // c offset
    const int n0 = blockIdx.x * 128;  // d offset
    const float* Ab = g_tmp + ((size_t)(b * LC + m0)) * LQ;
    const float* Bb = qry + (size_t)b * LQ * DD;

    const int tid = threadIdx.x;
    const int tx = tid & 15;
    const int ty = tid >> 4;

    float acc[8][8];
#pragma unroll
    for (int i = 0; i < 8; ++i)
#pragma unroll
        for (int j = 0; j < 8; ++j) acc[i][j] = 0.0f;

    for (int k0 = 0; k0 < LQ; k0 += 16) {
        // A tile: 128 rows x 16 k, float4 along k, store transposed
#pragma unroll
        for (int i = 0; i < 2; ++i) {
            int f   = tid + i * 256;
            int row = f >> 2;
            int kc  = (f & 3) * 4;
            float4 av = *(const float4*)(Ab + (size_t)row * LQ + k0 + kc);
            As[kc + 0][row] = av.x; As[kc + 1][row] = av.y;
            As[kc + 2][row] = av.z; As[kc + 3][row] = av.w;
        }
        // B tile: 16 rows (k) x 128 cols (n), contiguous along n
#pragma unroll
        for (int i = 0; i < 2; ++i) {
            int f  = tid + i * 256;
            int kr = f >> 5;            // 0..15
            int nc = (f & 31) * 4;      // 0..124
            float4 bv = *(const float4*)(Bb + (size_t)(k0 + kr) * DD + n0 + nc);
            *(float4*)&Bs[kr][nc] = bv;
        }
        __syncthreads();

#pragma unroll
        for (int k = 0; k < 16; ++k) {
            float ar[8], br[8];
            *(float4*)&ar[0] = *(const float4*)&As[k][ty * 8];
            *(float4*)&ar[4] = *(const float4*)&As[k][ty * 8 + 4];
            *(float4*)&br[0] = *(const float4*)&Bs[k][tx * 8];
            *(float4*)&br[4] = *(const float4*)&Bs[k][tx * 8 + 4];
#pragma unroll
            for (int i = 0; i < 8; ++i)
#pragma unroll
                for (int j = 0; j < 8; ++j)
                    acc[i][j] = fmaf(ar[i], br[j], acc[i][j]);
        }
        __syncthreads();
    }

#pragma unroll
    for (int i = 0; i < 8; ++i) {
        int c = m0 + ty * 8 + i;
        size_t base = ((size_t)(b * LC + c)) * DD + n0 + tx * 8;
        float4 c0 = *(const float4*)(ctx + base);
        float4 c1 = *(const float4*)(ctx + base + 4);
        float4 v0 = make_float4(acc[i][0] * c0.x, acc[i][1] * c0.y,
                                acc[i][2] * c0.z, acc[i][3] * c0.w);
        float4 v1 = make_float4(acc[i][4] * c1.x, acc[i][5] * c1.y,
                                acc[i][6] * c1.z, acc[i][7] * c1.w);
        *(float4*)(out + base)     = v0;
        *(float4*)(out + base + 4) = v1;
    }
}

extern "C" void kernel_launch(void* const* d_in, const int* in_sizes, int n_in,
                              void* d_out, int out_size) {
    (void)in_sizes; (void)n_in; (void)out_size;
    const float* ctx = (const float*)d_in[0];  // context_emb [8,2048,768]
    const float* qry = (const float*)d_in[1];  // query_emb   [8,512,768]
    float* out = (float*)d_out;                // [8,2048,768]

    dim3 blk(256);
    dim3 g1(LQ / 128, LC / 128, NB);   // (4,16,8)
    dim3 gs(NB * LC);                  // 16384 rows
    dim3 g2(DD / 128, LC / 128, NB);   // (6,16,8)

    k_gemm1<<<g1, blk>>>(ctx, qry);
    k_softmax<<<gs, blk>>>();
    k_gemm2<<<g2, blk>>>(ctx, qry, out);
}

// round 4
// speedup vs baseline: 2.7903x; 2.7903x over previous
#include <cuda_runtime.h>
#include <cuda_fp16.h>
#include <cstdint>

#define NB 8
#define LC 2048
#define LQ 512
#define DD 768

// ------------------------- device scratch (static) -------------------------
__device__ float g_tmp[NB * LC * LQ];                      // logits [b][c][q]
__device__ __align__(16) __half g_ctx_hi[NB * LC * DD];
__device__ __align__(16) __half g_ctx_lo[NB * LC * DD];
__device__ __align__(16) __half g_qry_hi[NB * LQ * DD];
__device__ __align__(16) __half g_qry_lo[NB * LQ * DD];
__device__ __align__(16) __half g_qryT_hi[NB * DD * LQ];   // [b][d][q]
__device__ __align__(16) __half g_qryT_lo[NB * DD * LQ];
__device__ __align__(16) __half g_alpha_hi[NB * LC * LQ];  // [b][c][q]
__device__ __align__(16) __half g_alpha_lo[NB * LC * LQ];

// ------------------------- helpers -------------------------
__device__ __forceinline__ uint32_t smem_u32(const void* p) {
    uint32_t a;
    asm("{ .reg .u64 t; cvta.to.shared.u64 t, %1; cvt.u32.u64 %0, t; }" : "=r"(a) : "l"(p));
    return a;
}
__device__ __forceinline__ void cpa16(uint32_t s, const void* g) {
    asm volatile("cp.async.cg.shared.global [%0], [%1], 16;" :: "r"(s), "l"(g));
}
#define CP_COMMIT() asm volatile("cp.async.commit_group;" ::: "memory")
#define CP_WAIT0()  asm volatile("cp.async.wait_group 0;" ::: "memory")
#define CP_WAIT1()  asm volatile("cp.async.wait_group 1;" ::: "memory")

__device__ __forceinline__ void ldsm4(uint32_t (&r)[4], uint32_t addr) {
    asm volatile("ldmatrix.sync.aligned.m8n8.x4.shared.b16 {%0,%1,%2,%3}, [%4];"
                 : "=r"(r[0]), "=r"(r[1]), "=r"(r[2]), "=r"(r[3]) : "r"(addr));
}
__device__ __forceinline__ void mma16816(float (&d)[4], const uint32_t (&a)[4],
                                         const uint32_t b0, const uint32_t b1) {
    asm volatile(
        "mma.sync.aligned.m16n8k16.row.col.f32.f16.f16.f32 "
        "{%0,%1,%2,%3}, {%4,%5,%6,%7}, {%8,%9}, {%0,%1,%2,%3};"
        : "+f"(d[0]), "+f"(d[1]), "+f"(d[2]), "+f"(d[3])
        : "r"(a[0]), "r"(a[1]), "r"(a[2]), "r"(a[3]), "r"(b0), "r"(b1));
}

// Swizzled byte offset inside a 128-row x 32-col(fp16) tile (64B rows, 16B chunks)
__device__ __forceinline__ uint32_t swoff(int r, int c) {
    return (uint32_t)((r * 4 + (c ^ ((r >> 1) & 3))) << 4);
}

// fp16 split
__device__ __forceinline__ void split2h(float x, __half& h, __half& l) {
    h = __float2half_rn(x);
    l = __float2half_rn(x - __half2float(h));
}
__device__ __forceinline__ uint32_t pkh(__half a, __half b) {
    uint16_t x = *(uint16_t*)&a, y = *(uint16_t*)&b;
    return (uint32_t)x | ((uint32_t)y << 16);
}

// ------------------------- conversion kernels -------------------------
__global__ __launch_bounds__(256) void k_split_ctx(const float* __restrict__ in) {
    int i = blockIdx.x * 256 + threadIdx.x;
    float4 v = ((const float4*)in)[i];
    __half h0, h1, h2, h3, l0, l1, l2, l3;
    split2h(v.x, h0, l0); split2h(v.y, h1, l1);
    split2h(v.z, h2, l2); split2h(v.w, h3, l3);
    ((uint2*)g_ctx_hi)[i] = make_uint2(pkh(h0, h1), pkh(h2, h3));
    ((uint2*)g_ctx_lo)[i] = make_uint2(pkh(l0, l1), pkh(l2, l3));
}
__global__ __launch_bounds__(256) void k_split_qry(const float* __restrict__ in) {
    int i = blockIdx.x * 256 + threadIdx.x;
    float4 v = ((const float4*)in)[i];
    __half h0, h1, h2, h3, l0, l1, l2, l3;
    split2h(v.x, h0, l0); split2h(v.y, h1, l1);
    split2h(v.z, h2, l2); split2h(v.w, h3, l3);
    ((uint2*)g_qry_hi)[i] = make_uint2(pkh(h0, h1), pkh(h2, h3));
    ((uint2*)g_qry_lo)[i] = make_uint2(pkh(l0, l1), pkh(l2, l3));
}
__global__ __launch_bounds__(256) void k_qryT(const float* __restrict__ qry) {
    __shared__ float t[32][33];
    int b = blockIdx.z;
    int d0 = blockIdx.x * 32, q0 = blockIdx.y * 32;
    int tx = threadIdx.x & 31, ty = threadIdx.x >> 5;
    const float* src = qry + (size_t)b * LQ * DD;
#pragma unroll
    for (int i = 0; i < 4; ++i)
        t[ty + 8 * i][tx] = src[(size_t)(q0 + ty + 8 * i) * DD + d0 + tx];
    __syncthreads();
#pragma unroll
    for (int i = 0; i < 4; ++i) {
        int d = d0 + ty + 8 * i;
        float v = t[tx][ty + 8 * i];
        __half h, l;
        split2h(v, h, l);
        size_t o = ((size_t)b * DD + d) * LQ + q0 + tx;
        g_qryT_hi[o] = h;
        g_qryT_lo[o] = l;
    }
}

// ------------------------- GEMM core -------------------------
// smem: per stage: Ah(8K) Al(8K) Bh(8K) Bl(8K) = 32K; two stages = 64K.
#define STG 32768

__device__ __forceinline__ void load_chunk(uint32_t sb,
                                           const __half* __restrict__ Ah,
                                           const __half* __restrict__ Al,
                                           const __half* __restrict__ Bh,
                                           const __half* __restrict__ Bl,
                                           int astr, int bstr, int k0, int tid) {
#pragma unroll
    for (int i = 0; i < 2; ++i) {
        int u = tid + i * 256;
        int r = u >> 2, c = u & 3;
        uint32_t sw = swoff(r, c);
        size_t ao = (size_t)r * astr + k0 + c * 8;
        size_t bo = (size_t)r * bstr + k0 + c * 8;
        cpa16(sb + 0 + sw, Ah + ao);
        cpa16(sb + 8192 + sw, Al + ao);
        cpa16(sb + 16384 + sw, Bh + bo);
        cpa16(sb + 24576 + sw, Bl + bo);
    }
}

__device__ __forceinline__ void mma_mainloop(float (&acc)[4][4][4], uint32_t sb,
                                             const __half* __restrict__ Ah,
                                             const __half* __restrict__ Al,
                                             const __half* __restrict__ Bh,
                                             const __half* __restrict__ Bl,
                                             int astr, int bstr, int nch, int tid) {
    const int wid = tid >> 5, l = tid & 31;
    const int wm = (wid & 1) * 64, wn = (wid >> 1) * 32;
    const int a_row = wm + (l & 15);
    const int a_ch = (l >> 4) & 1;
    const int b_row = wn + (l & 7) + ((l >> 4) << 3);
    const int b_ch = (l >> 3) & 1;

    load_chunk(sb, Ah, Al, Bh, Bl, astr, bstr, 0, tid);
    CP_COMMIT();

    int buf = 0;
    for (int ch = 0; ch < nch; ++ch) {
        if (ch + 1 < nch) {
            load_chunk(sb + (buf ^ 1) * STG, Ah, Al, Bh, Bl, astr, bstr, (ch + 1) * 32, tid);
            CP_COMMIT();
            CP_WAIT1();
        } else {
            CP_WAIT0();
        }
        __syncthreads();

        uint32_t s = sb + buf * STG;
#pragma unroll
        for (int kk = 0; kk < 2; ++kk) {
            uint32_t ah[4][4], al[4][4];
#pragma unroll
            for (int mt = 0; mt < 4; ++mt) {
                uint32_t off = swoff(a_row + mt * 16, kk * 2 + a_ch);
                ldsm4(ah[mt], s + off);
                ldsm4(al[mt], s + 8192 + off);
            }
            uint32_t bh0[4], bh1[4], bl0[4], bl1[4];
            {
                uint32_t off0 = swoff(b_row, kk * 2 + b_ch);
                uint32_t off1 = swoff(b_row + 16, kk * 2 + b_ch);
                ldsm4(bh0, s + 16384 + off0);
                ldsm4(bh1, s + 16384 + off1);
                ldsm4(bl0, s + 24576 + off0);
                ldsm4(bl1, s + 24576 + off1);
            }
            // b frags: n-tile 0:{bh0[0],bh0[1]} 1:{bh0[2],bh0[3]} 2:{bh1[0],bh1[1]} 3:{bh1[2],bh1[3]}
#pragma unroll
            for (int mt = 0; mt < 4; ++mt) {
#pragma unroll
                for (int nt = 0; nt < 4; ++nt) {
                    const uint32_t* ph = (nt < 2) ? bh0 : bh1;
                    const uint32_t* pl = (nt < 2) ? bl0 : bl1;
                    int o = (nt & 1) * 2;
                    mma16816(acc[mt][nt], ah[mt], ph[o], ph[o + 1]);
                    mma16816(acc[mt][nt], ah[mt], pl[o], pl[o + 1]);
                    mma16816(acc[mt][nt], al[mt], ph[o], ph[o + 1]);
                }
            }
        }
        __syncthreads();
        buf ^= 1;
    }
}

// ------------------------- GEMM1: logits -------------------------
__global__ __launch_bounds__(256) void k_gemm1_mma() {
    extern __shared__ char smem[];
    uint32_t sb = smem_u32(smem);
    const int tid = threadIdx.x;
    const int b = blockIdx.z, m0 = blockIdx.y * 128, n0 = blockIdx.x * 128;

    float acc[4][4][4];
#pragma unroll
    for (int i = 0; i < 4; ++i)
#pragma unroll
        for (int j = 0; j < 4; ++j)
#pragma unroll
            for (int k = 0; k < 4; ++k) acc[i][j][k] = 0.0f;

    mma_mainloop(acc, sb,
                 g_ctx_hi + ((size_t)b * LC + m0) * DD,
                 g_ctx_lo + ((size_t)b * LC + m0) * DD,
                 g_qry_hi + ((size_t)b * LQ + n0) * DD,
                 g_qry_lo + ((size_t)b * LQ + n0) * DD,
                 DD, DD, DD / 32, tid);

    const int wid = tid >> 5, l = tid & 31;
    const int wm = (wid & 1) * 64, wn = (wid >> 1) * 32;
#pragma unroll
    for (int mt = 0; mt < 4; ++mt) {
#pragma unroll
        for (int nt = 0; nt < 4; ++nt) {
            int row = m0 + wm + mt * 16 + (l >> 2);
            int col = n0 + wn + nt * 8 + (l & 3) * 2;
            float* p0 = g_tmp + ((size_t)b * LC + row) * LQ + col;
            float* p1 = g_tmp + ((size_t)b * LC + row + 8) * LQ + col;
            *(float2*)p0 = make_float2(acc[mt][nt][0], acc[mt][nt][1]);
            *(float2*)p1 = make_float2(acc[mt][nt][2], acc[mt][nt][3]);
        }
    }
}

// ------------------------- softmax over q -------------------------
__global__ __launch_bounds__(256) void k_softmax() {
    const int row = blockIdx.x;  // b*LC + c
    const float2* p = (const float2*)(g_tmp + (size_t)row * LQ);
    const int tid = threadIdx.x;

    float2 v = p[tid];
    float m = fmaxf(v.x, v.y);
#pragma unroll
    for (int o = 16; o > 0; o >>= 1) m = fmaxf(m, __shfl_xor_sync(0xffffffffu, m, o));

    __shared__ float smax[8];
    __shared__ float ssum[8];
    if ((tid & 31) == 0) smax[tid >> 5] = m;
    __syncthreads();
    float bm = smax[0];
#pragma unroll
    for (int i = 1; i < 8; ++i) bm = fmaxf(bm, smax[i]);

    float e0 = __expf(v.x - bm);
    float e1 = __expf(v.y - bm);
    float s = e0 + e1;
#pragma unroll
    for (int o = 16; o > 0; o >>= 1) s += __shfl_xor_sync(0xffffffffu, s, o);
    if ((tid & 31) == 0) ssum[tid >> 5] = s;
    __syncthreads();
    float bs = 0.0f;
#pragma unroll
    for (int i = 0; i < 8; ++i) bs += ssum[i];

    float inv = 1.0f / bs;
    float a0 = e0 * inv, a1 = e1 * inv;
    __half h0, h1, l0, l1;
    split2h(a0, h0, l0);
    split2h(a1, h1, l1);
    size_t w = (size_t)row * (LQ / 2) + tid;
    ((uint32_t*)g_alpha_hi)[w] = pkh(h0, h1);
    ((uint32_t*)g_alpha_lo)[w] = pkh(l0, l1);
}

// ------------------------- GEMM2 + gate -------------------------
__global__ __launch_bounds__(256) void k_gemm2_mma(const float* __restrict__ ctx,
                                                   float* __restrict__ out) {
    extern __shared__ char smem[];
    uint32_t sb = smem_u32(smem);
    const int tid = threadIdx.x;
    const int b = blockIdx.z, m0 = blockIdx.y * 128, n0 = blockIdx.x * 128;

    float acc[4][4][4];
#pragma unroll
    for (int i = 0; i < 4; ++i)
#pragma unroll
        for (int j = 0; j < 4; ++j)
#pragma unroll
            for (int k = 0; k < 4; ++k) acc[i][j][k] = 0.0f;

    mma_mainloop(acc, sb,
                 g_alpha_hi + ((size_t)b * LC + m0) * LQ,
                 g_alpha_lo + ((size_t)b * LC + m0) * LQ,
                 g_qryT_hi + ((size_t)b * DD + n0) * LQ,
                 g_qryT_lo + ((size_t)b * DD + n0) * LQ,
                 LQ, LQ, LQ / 32, tid);

    const int wid = tid >> 5, l = tid & 31;
    const int wm = (wid & 1) * 64, wn = (wid >> 1) * 32;
#pragma unroll
    for (int mt = 0; mt < 4; ++mt) {
#pragma unroll
        for (int nt = 0; nt < 4; ++nt) {
            int row = m0 + wm + mt * 16 + (l >> 2);
            int col = n0 + wn + nt * 8 + (l & 3) * 2;
            size_t o0 = ((size_t)b * LC + row) * DD + col;
            size_t o1 = ((size_t)b * LC + row + 8) * DD + col;
            float2 c0 = *(const float2*)(ctx + o0);
            float2 c1 = *(const float2*)(ctx + o1);
            *(float2*)(out + o0) = make_float2(acc[mt][nt][0] * c0.x, acc[mt][nt][1] * c0.y);
            *(float2*)(out + o1) = make_float2(acc[mt][nt][2] * c1.x, acc[mt][nt][3] * c1.y);
        }
    }
}

// ------------------------- launch -------------------------
extern "C" void kernel_launch(void* const* d_in, const int* in_sizes, int n_in,
                              void* d_out, int out_size) {
    (void)in_sizes; (void)n_in; (void)out_size;
    const float* ctx = (const float*)d_in[0];  // [8,2048,768]
    const float* qry = (const float*)d_in[1];  // [8,512,768]
    float* out = (float*)d_out;

    cudaFuncSetAttribute(k_gemm1_mma, cudaFuncAttributeMaxDynamicSharedMemorySize, 2 * STG);
    cudaFuncSetAttribute(k_gemm2_mma, cudaFuncAttributeMaxDynamicSharedMemorySize, 2 * STG);

    k_split_ctx<<<(NB * LC * DD) / (256 * 4), 256>>>(ctx);
    k_split_qry<<<(NB * LQ * DD) / (256 * 4), 256>>>(qry);
    k_qryT<<<dim3(DD / 32, LQ / 32, NB), 256>>>(qry);

    k_gemm1_mma<<<dim3(LQ / 128, LC / 128, NB), 256, 2 * STG>>>();
    k_softmax<<<NB * LC, 256>>>();
    k_gemm2_mma<<<dim3(DD / 128, LC / 128, NB), 256, 2 * STG>>>(ctx, out);
}

// round 5
// speedup vs baseline: 3.2067x; 1.1492x over previous
#include <cuda_runtime.h>
#include <cuda_fp16.h>
#include <cstdint>

#define NB 8
#define LC 2048
#define LQ 512
#define DD 768

// ------------------------- device scratch (static) -------------------------
__device__ float g_tmp[NB * LC * LQ];                      // logits [b][c][q]
__device__ __align__(16) __half g_ctx_hi[NB * LC * DD];
__device__ __align__(16) __half g_ctx_lo[NB * LC * DD];
__device__ __align__(16) __half g_qry_hi[NB * LQ * DD];
__device__ __align__(16) __half g_qry_lo[NB * LQ * DD];
__device__ __align__(16) __half g_qryT_hi[NB * DD * LQ];   // [b][d][q]
__device__ __align__(16) __half g_qryT_lo[NB * DD * LQ];
__device__ __align__(16) __half g_alpha_hi[NB * LC * LQ];  // [b][c][q]

// ------------------------- helpers -------------------------
__device__ __forceinline__ uint32_t smem_u32(const void* p) {
    uint32_t a;
    asm("{ .reg .u64 t; cvta.to.shared.u64 t, %1; cvt.u32.u64 %0, t; }" : "=r"(a) : "l"(p));
    return a;
}
__device__ __forceinline__ void cpa16(uint32_t s, const void* g) {
    asm volatile("cp.async.cg.shared.global [%0], [%1], 16;" :: "r"(s), "l"(g));
}
#define CP_COMMIT() asm volatile("cp.async.commit_group;" ::: "memory")
#define CP_WAIT0()  asm volatile("cp.async.wait_group 0;" ::: "memory")
#define CP_WAIT1()  asm volatile("cp.async.wait_group 1;" ::: "memory")

__device__ __forceinline__ void ldsm4(uint32_t (&r)[4], uint32_t addr) {
    asm volatile("ldmatrix.sync.aligned.m8n8.x4.shared.b16 {%0,%1,%2,%3}, [%4];"
                 : "=r"(r[0]), "=r"(r[1]), "=r"(r[2]), "=r"(r[3]) : "r"(addr));
}
__device__ __forceinline__ void mma16816(float (&d)[4], const uint32_t (&a)[4],
                                         const uint32_t b0, const uint32_t b1) {
    asm volatile(
        "mma.sync.aligned.m16n8k16.row.col.f32.f16.f16.f32 "
        "{%0,%1,%2,%3}, {%4,%5,%6,%7}, {%8,%9}, {%0,%1,%2,%3};"
        : "+f"(d[0]), "+f"(d[1]), "+f"(d[2]), "+f"(d[3])
        : "r"(a[0]), "r"(a[1]), "r"(a[2]), "r"(a[3]), "r"(b0), "r"(b1));
}

// Swizzled byte offset inside a 128-row x 32-col(fp16) tile (64B rows, 16B chunks)
__device__ __forceinline__ uint32_t swoff(int r, int c) {
    return (uint32_t)((r * 4 + (c ^ ((r >> 1) & 3))) << 4);
}

// fp16 split
__device__ __forceinline__ void split2h(float x, __half& h, __half& l) {
    h = __float2half_rn(x);
    l = __float2half_rn(x - __half2float(h));
}
__device__ __forceinline__ uint32_t pkh(__half a, __half b) {
    uint16_t x = *(uint16_t*)&a, y = *(uint16_t*)&b;
    return (uint32_t)x | ((uint32_t)y << 16);
}

// ------------------------- conversion kernels -------------------------
__global__ __launch_bounds__(256) void k_split_ctx(const float* __restrict__ in) {
    int i = blockIdx.x * 256 + threadIdx.x;
    float4 v = ((const float4*)in)[i];
    __half h0, h1, h2, h3, l0, l1, l2, l3;
    split2h(v.x, h0, l0); split2h(v.y, h1, l1);
    split2h(v.z, h2, l2); split2h(v.w, h3, l3);
    ((uint2*)g_ctx_hi)[i] = make_uint2(pkh(h0, h1), pkh(h2, h3));
    ((uint2*)g_ctx_lo)[i] = make_uint2(pkh(l0, l1), pkh(l2, l3));
}
__global__ __launch_bounds__(256) void k_split_qry(const float* __restrict__ in) {
    int i = blockIdx.x * 256 + threadIdx.x;
    float4 v = ((const float4*)in)[i];
    __half h0, h1, h2, h3, l0, l1, l2, l3;
    split2h(v.x, h0, l0); split2h(v.y, h1, l1);
    split2h(v.z, h2, l2); split2h(v.w, h3, l3);
    ((uint2*)g_qry_hi)[i] = make_uint2(pkh(h0, h1), pkh(h2, h3));
    ((uint2*)g_qry_lo)[i] = make_uint2(pkh(l0, l1), pkh(l2, l3));
}
__global__ __launch_bounds__(256) void k_qryT(const float* __restrict__ qry) {
    __shared__ float t[32][33];
    int b = blockIdx.z;
    int d0 = blockIdx.x * 32, q0 = blockIdx.y * 32;
    int tx = threadIdx.x & 31, ty = threadIdx.x >> 5;
    const float* src = qry + (size_t)b * LQ * DD;
#pragma unroll
    for (int i = 0; i < 4; ++i)
        t[ty + 8 * i][tx] = src[(size_t)(q0 + ty + 8 * i) * DD + d0 + tx];
    __syncthreads();
#pragma unroll
    for (int i = 0; i < 4; ++i) {
        int d = d0 + ty + 8 * i;
        float v = t[tx][ty + 8 * i];
        __half h, l;
        split2h(v, h, l);
        size_t o = ((size_t)b * DD + d) * LQ + q0 + tx;
        g_qryT_hi[o] = h;
        g_qryT_lo[o] = l;
    }
}

// ------------------------- GEMM core -------------------------
// per-stage smem layout (each operand tile = 128 rows x 32 halfs = 8KB)
template <bool ASPLIT>
struct Lay {
    static constexpr int OAH = 0;
    static constexpr int OAL = ASPLIT ? 8192 : 0;       // only if A split
    static constexpr int OBH = ASPLIT ? 16384 : 8192;
    static constexpr int OBL = OBH + 8192;
    static constexpr int STG = OBL + 8192;              // 32K or 24K
};

template <bool ASPLIT>
__device__ __forceinline__ void load_chunk(uint32_t sb,
                                           const __half* __restrict__ Ah,
                                           const __half* __restrict__ Al,
                                           const __half* __restrict__ Bh,
                                           const __half* __restrict__ Bl,
                                           int astr, int bstr, int k0, int tid) {
    using L = Lay<ASPLIT>;
#pragma unroll
    for (int i = 0; i < 2; ++i) {
        int u = tid + i * 256;
        int r = u >> 2, c = u & 3;
        uint32_t sw = swoff(r, c);
        size_t ao = (size_t)r * astr + k0 + c * 8;
        size_t bo = (size_t)r * bstr + k0 + c * 8;
        cpa16(sb + L::OAH + sw, Ah + ao);
        if (ASPLIT) cpa16(sb + L::OAL + sw, Al + ao);
        cpa16(sb + L::OBH + sw, Bh + bo);
        cpa16(sb + L::OBL + sw, Bl + bo);
    }
}

// 3-stage cp.async pipeline, one __syncthreads per chunk.
// Schedule at iter ch: wait(stage ch ready) -> sync -> issue load(ch+2) -> compute(ch).
// The sync guarantees all warps finished compute(ch-1), which owns the stage
// (ch+2)%3 == (ch-1)%3 being overwritten.
template <bool ASPLIT>
__device__ __forceinline__ void mma_mainloop(float (&acc)[4][4][4], uint32_t sb,
                                             const __half* __restrict__ Ah,
                                             const __half* __restrict__ Al,
                                             const __half* __restrict__ Bh,
                                             const __half* __restrict__ Bl,
                                             int astr, int bstr, int nch, int tid) {
    using L = Lay<ASPLIT>;
    const int wid = tid >> 5, l = tid & 31;
    const int wm = (wid & 1) * 64, wn = (wid >> 1) * 32;
    const int a_row = wm + (l & 15);
    const int a_ch = (l >> 4) & 1;
    const int b_row = wn + (l & 7) + ((l >> 4) << 3);
    const int b_ch = (l >> 3) & 1;

    load_chunk<ASPLIT>(sb, Ah, Al, Bh, Bl, astr, bstr, 0, tid);
    CP_COMMIT();
    load_chunk<ASPLIT>(sb + L::STG, Ah, Al, Bh, Bl, astr, bstr, 32, tid);
    CP_COMMIT();

    int stage = 0;
    for (int ch = 0; ch < nch; ++ch) {
        if (ch + 1 < nch) CP_WAIT1(); else CP_WAIT0();
        __syncthreads();
        if (ch + 2 < nch) {
            int ns = stage + 2; if (ns >= 3) ns -= 3;
            load_chunk<ASPLIT>(sb + ns * L::STG, Ah, Al, Bh, Bl, astr, bstr, (ch + 2) * 32, tid);
            CP_COMMIT();
        }

        uint32_t s = sb + stage * L::STG;
#pragma unroll
        for (int kk = 0; kk < 2; ++kk) {
            uint32_t ah[4][4], al[4][4];
#pragma unroll
            for (int mt = 0; mt < 4; ++mt) {
                uint32_t off = swoff(a_row + mt * 16, kk * 2 + a_ch);
                ldsm4(ah[mt], s + L::OAH + off);
                if (ASPLIT) ldsm4(al[mt], s + L::OAL + off);
            }
            uint32_t bh0[4], bh1[4], bl0[4], bl1[4];
            {
                uint32_t off0 = swoff(b_row, kk * 2 + b_ch);
                uint32_t off1 = swoff(b_row + 16, kk * 2 + b_ch);
                ldsm4(bh0, s + L::OBH + off0);
                ldsm4(bh1, s + L::OBH + off1);
                ldsm4(bl0, s + L::OBL + off0);
                ldsm4(bl1, s + L::OBL + off1);
            }
#pragma unroll
            for (int mt = 0; mt < 4; ++mt) {
#pragma unroll
                for (int nt = 0; nt < 4; ++nt) {
                    const uint32_t* ph = (nt < 2) ? bh0 : bh1;
                    const uint32_t* pl = (nt < 2) ? bl0 : bl1;
                    int o = (nt & 1) * 2;
                    mma16816(acc[mt][nt], ah[mt], ph[o], ph[o + 1]);
                    mma16816(acc[mt][nt], ah[mt], pl[o], pl[o + 1]);
                    if (ASPLIT) mma16816(acc[mt][nt], al[mt], ph[o], ph[o + 1]);
                }
            }
        }
        ++stage; if (stage == 3) stage = 0;
    }
}

// ------------------------- GEMM1: logits -------------------------
__global__ __launch_bounds__(256) void k_gemm1_mma() {
    extern __shared__ char smem[];
    uint32_t sb = smem_u32(smem);
    const int tid = threadIdx.x;
    const int b = blockIdx.z, m0 = blockIdx.y * 128, n0 = blockIdx.x * 128;

    float acc[4][4][4];
#pragma unroll
    for (int i = 0; i < 4; ++i)
#pragma unroll
        for (int j = 0; j < 4; ++j)
#pragma unroll
            for (int k = 0; k < 4; ++k) acc[i][j][k] = 0.0f;

    mma_mainloop<true>(acc, sb,
                       g_ctx_hi + ((size_t)b * LC + m0) * DD,
                       g_ctx_lo + ((size_t)b * LC + m0) * DD,
                       g_qry_hi + ((size_t)b * LQ + n0) * DD,
                       g_qry_lo + ((size_t)b * LQ + n0) * DD,
                       DD, DD, DD / 32, tid);

    const int wid = tid >> 5, l = tid & 31;
    const int wm = (wid & 1) * 64, wn = (wid >> 1) * 32;
#pragma unroll
    for (int mt = 0; mt < 4; ++mt) {
#pragma unroll
        for (int nt = 0; nt < 4; ++nt) {
            int row = m0 + wm + mt * 16 + (l >> 2);
            int col = n0 + wn + nt * 8 + (l & 3) * 2;
            float* p0 = g_tmp + ((size_t)b * LC + row) * LQ + col;
            float* p1 = g_tmp + ((size_t)b * LC + row + 8) * LQ + col;
            *(float2*)p0 = make_float2(acc[mt][nt][0], acc[mt][nt][1]);
            *(float2*)p1 = make_float2(acc[mt][nt][2], acc[mt][nt][3]);
        }
    }
}

// ------------------------- softmax over q -------------------------
__global__ __launch_bounds__(256) void k_softmax() {
    const int row = blockIdx.x;  // b*LC + c
    const float2* p = (const float2*)(g_tmp + (size_t)row * LQ);
    const int tid = threadIdx.x;

    float2 v = p[tid];
    float m = fmaxf(v.x, v.y);
#pragma unroll
    for (int o = 16; o > 0; o >>= 1) m = fmaxf(m, __shfl_xor_sync(0xffffffffu, m, o));

    __shared__ float smax[8];
    __shared__ float ssum[8];
    if ((tid & 31) == 0) smax[tid >> 5] = m;
    __syncthreads();
    float bm = smax[0];
#pragma unroll
    for (int i = 1; i < 8; ++i) bm = fmaxf(bm, smax[i]);

    float e0 = __expf(v.x - bm);
    float e1 = __expf(v.y - bm);
    float s = e0 + e1;
#pragma unroll
    for (int o = 16; o > 0; o >>= 1) s += __shfl_xor_sync(0xffffffffu, s, o);
    if ((tid & 31) == 0) ssum[tid >> 5] = s;
    __syncthreads();
    float bs = 0.0f;
#pragma unroll
    for (int i = 0; i < 8; ++i) bs += ssum[i];

    float inv = 1.0f / bs;
    ((uint32_t*)g_alpha_hi)[(size_t)row * (LQ / 2) + tid] =
        pkh(__float2half_rn(e0 * inv), __float2half_rn(e1 * inv));
}

// ------------------------- GEMM2 + gate (A = alpha hi only) ---------------
__global__ __launch_bounds__(256) void k_gemm2_mma(const float* __restrict__ ctx,
                                                   float* __restrict__ out) {
    extern __shared__ char smem[];
    uint32_t sb = smem_u32(smem);
    const int tid = threadIdx.x;
    const int b = blockIdx.z, m0 = blockIdx.y * 128, n0 = blockIdx.x * 128;

    float acc[4][4][4];
#pragma unroll
    for (int i = 0; i < 4; ++i)
#pragma unroll
        for (int j = 0; j < 4; ++j)
#pragma unroll
            for (int k = 0; k < 4; ++k) acc[i][j][k] = 0.0f;

    mma_mainloop<false>(acc, sb,
                        g_alpha_hi + ((size_t)b * LC + m0) * LQ,
                        nullptr,
                        g_qryT_hi + ((size_t)b * DD + n0) * LQ,
                        g_qryT_lo + ((size_t)b * DD + n0) * LQ,
                        LQ, LQ, LQ / 32, tid);

    const int wid = tid >> 5, l = tid & 31;
    const int wm = (wid & 1) * 64, wn = (wid >> 1) * 32;
#pragma unroll
    for (int mt = 0; mt < 4; ++mt) {
#pragma unroll
        for (int nt = 0; nt < 4; ++nt) {
            int row = m0 + wm + mt * 16 + (l >> 2);
            int col = n0 + wn + nt * 8 + (l & 3) * 2;
            size_t o0 = ((size_t)b * LC + row) * DD + col;
            size_t o1 = ((size_t)b * LC + row + 8) * DD + col;
            float2 c0 = *(const float2*)(ctx + o0);
            float2 c1 = *(const float2*)(ctx + o1);
            *(float2*)(out + o0) = make_float2(acc[mt][nt][0] * c0.x, acc[mt][nt][1] * c0.y);
            *(float2*)(out + o1) = make_float2(acc[mt][nt][2] * c1.x, acc[mt][nt][3] * c1.y);
        }
    }
}

// ------------------------- launch -------------------------
extern "C" void kernel_launch(void* const* d_in, const int* in_sizes, int n_in,
                              void* d_out, int out_size) {
    (void)in_sizes; (void)n_in; (void)out_size;
    const float* ctx = (const float*)d_in[0];  // [8,2048,768]
    const float* qry = (const float*)d_in[1];  // [8,512,768]
    float* out = (float*)d_out;

    const int smem1 = 3 * Lay<true>::STG;   // 98304
    const int smem2 = 3 * Lay<false>::STG;  // 73728
    cudaFuncSetAttribute(k_gemm1_mma, cudaFuncAttributeMaxDynamicSharedMemorySize, smem1);
    cudaFuncSetAttribute(k_gemm2_mma, cudaFuncAttributeMaxDynamicSharedMemorySize, smem2);

    k_split_ctx<<<(NB * LC * DD) / (256 * 4), 256>>>(ctx);
    k_split_qry<<<(NB * LQ * DD) / (256 * 4), 256>>>(qry);
    k_qryT<<<dim3(DD / 32, LQ / 32, NB), 256>>>(qry);

    k_gemm1_mma<<<dim3(LQ / 128, LC / 128, NB), 256, smem1>>>();
    k_softmax<<<NB * LC, 256>>>();
    k_gemm2_mma<<<dim3(DD / 128, LC / 128, NB), 256, smem2>>>(ctx, out);
}

// round 6
// speedup vs baseline: 3.2800x; 1.0229x over previous
#include <cuda_runtime.h>
#include <cuda_fp16.h>
#include <cstdint>

#define NB 8
#define LC 2048
#define LQ 512
#define DD 768

// ------------------------- device scratch (static) -------------------------
__device__ float g_tmp[NB * LC * LQ];                      // logits [b][c][q]
__device__ __align__(16) __half g_ctx_hi[NB * LC * DD];
__device__ __align__(16) __half g_ctx_lo[NB * LC * DD];
__device__ __align__(16) __half g_qry_hi[NB * LQ * DD];
__device__ __align__(16) __half g_qry_lo[NB * LQ * DD];
__device__ __align__(16) __half g_qryT_hi[NB * DD * LQ];   // [b][d][q]
__device__ __align__(16) __half g_qryT_lo[NB * DD * LQ];
__device__ __align__(16) __half g_alpha_hi[NB * LC * LQ];  // [b][c][q]

// ------------------------- helpers -------------------------
__device__ __forceinline__ uint32_t smem_u32(const void* p) {
    uint32_t a;
    asm("{ .reg .u64 t; cvta.to.shared.u64 t, %1; cvt.u32.u64 %0, t; }" : "=r"(a) : "l"(p));
    return a;
}
__device__ __forceinline__ void cpa16(uint32_t s, const void* g) {
    asm volatile("cp.async.cg.shared.global [%0], [%1], 16;" :: "r"(s), "l"(g));
}
#define CP_COMMIT() asm volatile("cp.async.commit_group;" ::: "memory")
#define CP_WAIT0()  asm volatile("cp.async.wait_group 0;" ::: "memory")
#define CP_WAIT1()  asm volatile("cp.async.wait_group 1;" ::: "memory")

__device__ __forceinline__ void ldsm4(uint32_t* r, uint32_t addr) {
    asm volatile("ldmatrix.sync.aligned.m8n8.x4.shared.b16 {%0,%1,%2,%3}, [%4];"
                 : "=r"(r[0]), "=r"(r[1]), "=r"(r[2]), "=r"(r[3]) : "r"(addr));
}
__device__ __forceinline__ void mma16816(float* d, const uint32_t* a,
                                         const uint32_t b0, const uint32_t b1) {
    asm volatile(
        "mma.sync.aligned.m16n8k16.row.col.f32.f16.f16.f32 "
        "{%0,%1,%2,%3}, {%4,%5,%6,%7}, {%8,%9}, {%0,%1,%2,%3};"
        : "+f"(d[0]), "+f"(d[1]), "+f"(d[2]), "+f"(d[3])
        : "r"(a[0]), "r"(a[1]), "r"(a[2]), "r"(a[3]), "r"(b0), "r"(b1));
}

// Swizzled byte offset inside a 128-row x 32-col(fp16) tile (64B rows, 16B chunks)
__device__ __forceinline__ uint32_t swoff(int r, int c) {
    return (uint32_t)((r * 4 + (c ^ ((r >> 1) & 3))) << 4);
}

// fp16 split
__device__ __forceinline__ void split2h(float x, __half& h, __half& l) {
    h = __float2half_rn(x);
    l = __float2half_rn(x - __half2float(h));
}
__device__ __forceinline__ uint32_t pkh(__half a, __half b) {
    uint16_t x = *(uint16_t*)&a, y = *(uint16_t*)&b;
    return (uint32_t)x | ((uint32_t)y << 16);
}

// ------------------------- conversion kernels -------------------------
__global__ __launch_bounds__(256) void k_split_ctx(const float* __restrict__ in) {
    int i = blockIdx.x * 256 + threadIdx.x;
    float4 v = ((const float4*)in)[i];
    __half h0, h1, h2, h3, l0, l1, l2, l3;
    split2h(v.x, h0, l0); split2h(v.y, h1, l1);
    split2h(v.z, h2, l2); split2h(v.w, h3, l3);
    ((uint2*)g_ctx_hi)[i] = make_uint2(pkh(h0, h1), pkh(h2, h3));
    ((uint2*)g_ctx_lo)[i] = make_uint2(pkh(l0, l1), pkh(l2, l3));
}

// Fused: split qry (row-major) AND produce transposed split copies.
// 32x32 tile per block, 256 threads (32x8).
__global__ __launch_bounds__(256) void k_split_qry_both(const float* __restrict__ qry) {
    __shared__ float t[32][33];
    int b = blockIdx.z;
    int d0 = blockIdx.x * 32, q0 = blockIdx.y * 32;
    int tx = threadIdx.x & 31, ty = threadIdx.x >> 5;
    const float* src = qry + (size_t)b * LQ * DD;
#pragma unroll
    for (int i = 0; i < 4; ++i) {
        int q = q0 + ty + 8 * i;
        float v = src[(size_t)q * DD + d0 + tx];
        t[ty + 8 * i][tx] = v;
        __half h, l;
        split2h(v, h, l);
        size_t o = (size_t)(b * LQ + q) * DD + d0 + tx;
        g_qry_hi[o] = h;
        g_qry_lo[o] = l;
    }
    __syncthreads();
#pragma unroll
    for (int i = 0; i < 4; ++i) {
        int d = d0 + ty + 8 * i;
        float v = t[tx][ty + 8 * i];
        __half h, l;
        split2h(v, h, l);
        size_t o = ((size_t)b * DD + d) * LQ + q0 + tx;
        g_qryT_hi[o] = h;
        g_qryT_lo[o] = l;
    }
}

// ------------------------- GEMM core -------------------------
// CTA 128x128, 4 warps (2x2), warp tile 64x64, BK=32, 3-stage cp.async.
template <bool ASPLIT>
struct Lay {
    static constexpr int OAH = 0;
    static constexpr int OAL = ASPLIT ? 8192 : 0;
    static constexpr int OBH = ASPLIT ? 16384 : 8192;
    static constexpr int OBL = OBH + 8192;
    static constexpr int STG = OBL + 8192;   // 32K (split A) or 24K
};

template <bool ASPLIT>
__device__ __forceinline__ void load_chunk(uint32_t sb,
                                           const __half* __restrict__ Ah,
                                           const __half* __restrict__ Al,
                                           const __half* __restrict__ Bh,
                                           const __half* __restrict__ Bl,
                                           int astr, int bstr, int k0, int tid) {
    using L = Lay<ASPLIT>;
#pragma unroll
    for (int i = 0; i < 4; ++i) {
        int u = tid + i * 128;          // 0..511
        int r = u >> 2, c = u & 3;
        uint32_t sw = swoff(r, c);
        size_t ao = (size_t)r * astr + k0 + c * 8;
        size_t bo = (size_t)r * bstr + k0 + c * 8;
        cpa16(sb + L::OAH + sw, Ah + ao);
        if (ASPLIT) cpa16(sb + L::OAL + sw, Al + ao);
        cpa16(sb + L::OBH + sw, Bh + bo);
        cpa16(sb + L::OBL + sw, Bl + bo);
    }
}

// acc layout: acc[mt][nt][4], mt 0..3 (m16), nt 0..7 (n8)
template <bool ASPLIT>
__device__ __forceinline__ void mma_mainloop(float (&acc)[4][8][4], uint32_t sb,
                                             const __half* __restrict__ Ah,
                                             const __half* __restrict__ Al,
                                             const __half* __restrict__ Bh,
                                             const __half* __restrict__ Bl,
                                             int astr, int bstr, int nch, int tid) {
    using L = Lay<ASPLIT>;
    const int wid = tid >> 5, l = tid & 31;
    const int wm = (wid & 1) * 64, wn = (wid >> 1) * 64;
    const int a_row = wm + (l & 15);
    const int a_ch = (l >> 4) & 1;
    const int b_row = wn + (l & 7) + ((l >> 4) << 3);
    const int b_ch = (l >> 3) & 1;

    load_chunk<ASPLIT>(sb, Ah, Al, Bh, Bl, astr, bstr, 0, tid);
    CP_COMMIT();
    load_chunk<ASPLIT>(sb + L::STG, Ah, Al, Bh, Bl, astr, bstr, 32, tid);
    CP_COMMIT();

    int stage = 0;
    for (int ch = 0; ch < nch; ++ch) {
        if (ch + 1 < nch) CP_WAIT1(); else CP_WAIT0();
        __syncthreads();
        if (ch + 2 < nch) {
            int ns = stage + 2; if (ns >= 3) ns -= 3;
            load_chunk<ASPLIT>(sb + ns * L::STG, Ah, Al, Bh, Bl, astr, bstr, (ch + 2) * 32, tid);
            CP_COMMIT();
        }

        uint32_t s = sb + stage * L::STG;
#pragma unroll
        for (int kk = 0; kk < 2; ++kk) {
            uint32_t ah[16], al[16];
#pragma unroll
            for (int mt = 0; mt < 4; ++mt) {
                uint32_t off = swoff(a_row + mt * 16, kk * 2 + a_ch);
                ldsm4(&ah[mt * 4], s + L::OAH + off);
                if (ASPLIT) ldsm4(&al[mt * 4], s + L::OAL + off);
            }
            uint32_t bh[16], bl[16];
#pragma unroll
            for (int g = 0; g < 4; ++g) {
                uint32_t off = swoff(b_row + g * 16, kk * 2 + b_ch);
                ldsm4(&bh[g * 4], s + L::OBH + off);
                ldsm4(&bl[g * 4], s + L::OBL + off);
            }
            // term-major: consecutive MMAs hit different accumulators
#pragma unroll
            for (int mt = 0; mt < 4; ++mt)
#pragma unroll
                for (int nt = 0; nt < 8; ++nt)
                    mma16816(acc[mt][nt], &ah[mt * 4], bh[nt * 2], bh[nt * 2 + 1]);
#pragma unroll
            for (int mt = 0; mt < 4; ++mt)
#pragma unroll
                for (int nt = 0; nt < 8; ++nt)
                    mma16816(acc[mt][nt], &ah[mt * 4], bl[nt * 2], bl[nt * 2 + 1]);
            if (ASPLIT) {
#pragma unroll
                for (int mt = 0; mt < 4; ++mt)
#pragma unroll
                    for (int nt = 0; nt < 8; ++nt)
                        mma16816(acc[mt][nt], &al[mt * 4], bh[nt * 2], bh[nt * 2 + 1]);
            }
        }
        ++stage; if (stage == 3) stage = 0;
    }
}

// ------------------------- GEMM1: logits -------------------------
__global__ __launch_bounds__(128, 2) void k_gemm1_mma() {
    extern __shared__ char smem[];
    uint32_t sb = smem_u32(smem);
    const int tid = threadIdx.x;
    const int b = blockIdx.z, m0 = blockIdx.y * 128, n0 = blockIdx.x * 128;

    float acc[4][8][4];
#pragma unroll
    for (int i = 0; i < 4; ++i)
#pragma unroll
        for (int j = 0; j < 8; ++j)
#pragma unroll
            for (int k = 0; k < 4; ++k) acc[i][j][k] = 0.0f;

    mma_mainloop<true>(acc, sb,
                       g_ctx_hi + ((size_t)b * LC + m0) * DD,
                       g_ctx_lo + ((size_t)b * LC + m0) * DD,
                       g_qry_hi + ((size_t)b * LQ + n0) * DD,
                       g_qry_lo + ((size_t)b * LQ + n0) * DD,
                       DD, DD, DD / 32, tid);

    const int wid = tid >> 5, l = tid & 31;
    const int wm = (wid & 1) * 64, wn = (wid >> 1) * 64;
#pragma unroll
    for (int mt = 0; mt < 4; ++mt) {
#pragma unroll
        for (int nt = 0; nt < 8; ++nt) {
            int row = m0 + wm + mt * 16 + (l >> 2);
            int col = n0 + wn + nt * 8 + (l & 3) * 2;
            float* p0 = g_tmp + ((size_t)b * LC + row) * LQ + col;
            float* p1 = g_tmp + ((size_t)b * LC + row + 8) * LQ + col;
            *(float2*)p0 = make_float2(acc[mt][nt][0], acc[mt][nt][1]);
            *(float2*)p1 = make_float2(acc[mt][nt][2], acc[mt][nt][3]);
        }
    }
}

// ------------------------- softmax over q -------------------------
__global__ __launch_bounds__(256) void k_softmax() {
    const int row = blockIdx.x;  // b*LC + c
    const float2* p = (const float2*)(g_tmp + (size_t)row * LQ);
    const int tid = threadIdx.x;

    float2 v = p[tid];
    float m = fmaxf(v.x, v.y);
#pragma unroll
    for (int o = 16; o > 0; o >>= 1) m = fmaxf(m, __shfl_xor_sync(0xffffffffu, m, o));

    __shared__ float smax[8];
    __shared__ float ssum[8];
    if ((tid & 31) == 0) smax[tid >> 5] = m;
    __syncthreads();
    float bm = smax[0];
#pragma unroll
    for (int i = 1; i < 8; ++i) bm = fmaxf(bm, smax[i]);

    float e0 = __expf(v.x - bm);
    float e1 = __expf(v.y - bm);
    float s = e0 + e1;
#pragma unroll
    for (int o = 16; o > 0; o >>= 1) s += __shfl_xor_sync(0xffffffffu, s, o);
    if ((tid & 31) == 0) ssum[tid >> 5] = s;
    __syncthreads();
    float bs = 0.0f;
#pragma unroll
    for (int i = 0; i < 8; ++i) bs += ssum[i];

    float inv = 1.0f / bs;
    ((uint32_t*)g_alpha_hi)[(size_t)row * (LQ / 2) + tid] =
        pkh(__float2half_rn(e0 * inv), __float2half_rn(e1 * inv));
}

// ------------------------- GEMM2 + gate (A = alpha hi only) ---------------
__global__ __launch_bounds__(128, 2) void k_gemm2_mma(const float* __restrict__ ctx,
                                                      float* __restrict__ out) {
    extern __shared__ char smem[];
    uint32_t sb = smem_u32(smem);
    const int tid = threadIdx.x;
    const int b = blockIdx.z, m0 = blockIdx.y * 128, n0 = blockIdx.x * 128;

    float acc[4][8][4];
#pragma unroll
    for (int i = 0; i < 4; ++i)
#pragma unroll
        for (int j = 0; j < 8; ++j)
#pragma unroll
            for (int k = 0; k < 4; ++k) acc[i][j][k] = 0.0f;

    mma_mainloop<false>(acc, sb,
                        g_alpha_hi + ((size_t)b * LC + m0) * LQ,
                        nullptr,
                        g_qryT_hi + ((size_t)b * DD + n0) * LQ,
                        g_qryT_lo + ((size_t)b * DD + n0) * LQ,
                        LQ, LQ, LQ / 32, tid);

    const int wid = tid >> 5, l = tid & 31;
    const int wm = (wid & 1) * 64, wn = (wid >> 1) * 64;
#pragma unroll
    for (int mt = 0; mt < 4; ++mt) {
#pragma unroll
        for (int nt = 0; nt < 8; ++nt) {
            int row = m0 + wm + mt * 16 + (l >> 2);
            int col = n0 + wn + nt * 8 + (l & 3) * 2;
            size_t o0 = ((size_t)b * LC + row) * DD + col;
            size_t o1 = ((size_t)b * LC + row + 8) * DD + col;
            float2 c0 = *(const float2*)(ctx + o0);
            float2 c1 = *(const float2*)(ctx + o1);
            *(float2*)(out + o0) = make_float2(acc[mt][nt][0] * c0.x, acc[mt][nt][1] * c0.y);
            *(float2*)(out + o1) = make_float2(acc[mt][nt][2] * c1.x, acc[mt][nt][3] * c1.y);
        }
    }
}

// ------------------------- launch -------------------------
extern "C" void kernel_launch(void* const* d_in, const int* in_sizes, int n_in,
                              void* d_out, int out_size) {
    (void)in_sizes; (void)n_in; (void)out_size;
    const float* ctx = (const float*)d_in[0];  // [8,2048,768]
    const float* qry = (const float*)d_in[1];  // [8,512,768]
    float* out = (float*)d_out;

    const int smem1 = 3 * Lay<true>::STG;   // 98304
    const int smem2 = 3 * Lay<false>::STG;  // 73728
    cudaFuncSetAttribute(k_gemm1_mma, cudaFuncAttributeMaxDynamicSharedMemorySize, smem1);
    cudaFuncSetAttribute(k_gemm2_mma, cudaFuncAttributeMaxDynamicSharedMemorySize, smem2);

    k_split_ctx<<<(NB * LC * DD) / (256 * 4), 256>>>(ctx);
    k_split_qry_both<<<dim3(DD / 32, LQ / 32, NB), 256>>>(qry);

    k_gemm1_mma<<<dim3(LQ / 128, LC / 128, NB), 128, smem1>>>();
    k_softmax<<<NB * LC, 256>>>();
    k_gemm2_mma<<<dim3(DD / 128, LC / 128, NB), 128, smem2>>>(ctx, out);
}